// round 1
// baseline (speedup 1.0000x reference)
#include <cuda_runtime.h>
#include <math.h>

// Problem constants
#define Bb 32
#define Nn 4096
#define Dd 256
#define Ss 16
#define Hh 512
#define NITERS 3
#define RBN (Bb*Nn)   // 131072 token rows
#define RBS (Bb*Ss)   // 512 slot rows

// ---------------- scratch (device globals; no allocation allowed) ----------------
__device__ float g_xln [RBN*Dd];     // LN(inputs)
__device__ float g_k   [RBN*Dd];
__device__ float g_v   [RBN*Dd];
__device__ float g_attn[RBN*Ss];     // softmax*tw (pre token-normalization)
__device__ float g_colsum[RBS];
__device__ float g_rinv  [RBS];
__device__ float g_slots [RBS*Dd];
__device__ float g_slots2[RBS*Dd];
__device__ float g_sln   [RBS*Dd];
__device__ float g_q     [RBS*Dd];
__device__ float g_upd   [RBS*Dd];
__device__ float g_gi    [RBS*3*Dd];
__device__ float g_gh    [RBS*3*Dd];
__device__ float g_hbuf  [RBS*Hh];

// ---------------- LayerNorm over rows of length 256 ----------------
__global__ void ln_rows(const float* __restrict__ x, float* __restrict__ y,
                        const float* __restrict__ w, const float* __restrict__ bias) {
    __shared__ float red[256];
    int row = blockIdx.x, t = threadIdx.x;
    size_t base = (size_t)row * Dd;
    float v = x[base + t];
    red[t] = v; __syncthreads();
    #pragma unroll
    for (int o = 128; o > 0; o >>= 1) { if (t < o) red[t] += red[t + o]; __syncthreads(); }
    float mean = red[0] * (1.0f / Dd);
    __syncthreads();
    float d = v - mean;
    red[t] = d * d; __syncthreads();
    #pragma unroll
    for (int o = 128; o > 0; o >>= 1) { if (t < o) red[t] += red[t + o]; __syncthreads(); }
    float rstd = rsqrtf(red[0] * (1.0f / Dd) + 1e-5f);
    y[base + t] = d * rstd * w[t] + bias[t];
}

// ---------------- big SGEMM: [131072,256] x [256,(256|256)] -> k,v ----------------
// C = A @ W^T.  bx in {0,1}: Wk cols [0,128)/[128,256); bx in {2,3}: Wv.
// 128x128 tile, BK=8, 256 threads, 8x8 microtile, ping-pong smem + reg prefetch.
__global__ void __launch_bounds__(256, 2) sgemm_kv(const float* __restrict__ A,
        const float* __restrict__ Wk, const float* __restrict__ Wv) {
    __shared__ float As[2][8][128];
    __shared__ float Bs[2][8][128];
    int tid = threadIdx.x;
    int tx = tid & 15, ty = tid >> 4;
    int bx = blockIdx.x;
    size_t m0 = (size_t)blockIdx.y * 128;
    const float* Wb = (bx < 2) ? Wk : Wv;
    float* Out = (bx < 2) ? g_k : g_v;
    int n0 = (bx & 1) * 128;
    int lr = tid >> 1;           // 0..127
    int lc = (tid & 1) * 4;      // 0 or 4
    const float* Ap = A  + (m0 + lr) * Dd + lc;
    const float* Bp = Wb + (size_t)(n0 + lr) * Dd + lc;
    float acc[8][8];
    #pragma unroll
    for (int i = 0; i < 8; i++)
        #pragma unroll
        for (int j = 0; j < 8; j++) acc[i][j] = 0.f;

    float4 a4 = *(const float4*)(Ap);
    float4 b4 = *(const float4*)(Bp);
    As[0][lc+0][lr]=a4.x; As[0][lc+1][lr]=a4.y; As[0][lc+2][lr]=a4.z; As[0][lc+3][lr]=a4.w;
    Bs[0][lc+0][lr]=b4.x; Bs[0][lc+1][lr]=b4.y; Bs[0][lc+2][lr]=b4.z; Bs[0][lc+3][lr]=b4.w;
    __syncthreads();

    #pragma unroll 1
    for (int t = 0; t < 32; t++) {
        int cur = t & 1;
        if (t < 31) {
            int k0 = (t + 1) * 8;
            a4 = *(const float4*)(Ap + k0);
            b4 = *(const float4*)(Bp + k0);
        }
        #pragma unroll
        for (int kk = 0; kk < 8; kk++) {
            float ra[8], rb[8];
            *(float4*)(ra)     = *(const float4*)&As[cur][kk][ty*4];
            *(float4*)(ra + 4) = *(const float4*)&As[cur][kk][64 + ty*4];
            *(float4*)(rb)     = *(const float4*)&Bs[cur][kk][tx*4];
            *(float4*)(rb + 4) = *(const float4*)&Bs[cur][kk][64 + tx*4];
            #pragma unroll
            for (int i = 0; i < 8; i++)
                #pragma unroll
                for (int j = 0; j < 8; j++) acc[i][j] += ra[i] * rb[j];
        }
        if (t < 31) {
            int nb = cur ^ 1;
            As[nb][lc+0][lr]=a4.x; As[nb][lc+1][lr]=a4.y; As[nb][lc+2][lr]=a4.z; As[nb][lc+3][lr]=a4.w;
            Bs[nb][lc+0][lr]=b4.x; Bs[nb][lc+1][lr]=b4.y; Bs[nb][lc+2][lr]=b4.z; Bs[nb][lc+3][lr]=b4.w;
            __syncthreads();
        }
    }
    #pragma unroll
    for (int i = 0; i < 8; i++) {
        int rr = (i < 4) ? (ty*4 + i) : (64 + ty*4 + (i - 4));
        size_t m = m0 + rr;
        float* op = Out + m * Dd + n0;
        *(float4*)(op + tx*4)      = make_float4(acc[i][0], acc[i][1], acc[i][2], acc[i][3]);
        *(float4*)(op + 64 + tx*4) = make_float4(acc[i][4], acc[i][5], acc[i][6], acc[i][7]);
    }
}

// ---------------- generic small SGEMM: C = act(A@B^T + bias) (+Cadd) ----------------
// 64x64 tile, BK=16, 256 threads, 4x4 microtile. M,Ncols multiples of 64; K of 16.
// rscale: optional per-row scale applied to A (used for colsum division).
// act: 0 = none, 1 = exact gelu.
__global__ void __launch_bounds__(256) gemm64(const float* __restrict__ A,
        const float* __restrict__ Bw, const float* __restrict__ bias,
        const float* __restrict__ rscale, const float* __restrict__ Cadd,
        float* __restrict__ C, int M, int Ncols, int K, int act) {
    __shared__ float As[16][64];
    __shared__ float Bs[16][64];
    int tid = threadIdx.x;
    int tx = tid & 15, ty = tid >> 4;
    int m0 = blockIdx.y * 64, n0 = blockIdx.x * 64;
    int lr = tid >> 2;           // 0..63
    int lc = (tid & 3) * 4;      // 0,4,8,12
    float rs = rscale ? rscale[m0 + lr] : 1.0f;
    const float* Ap = A  + (size_t)(m0 + lr) * K + lc;
    const float* Bp = Bw + (size_t)(n0 + lr) * K + lc;
    float acc[4][4];
    #pragma unroll
    for (int i = 0; i < 4; i++)
        #pragma unroll
        for (int j = 0; j < 4; j++) acc[i][j] = 0.f;

    for (int k0 = 0; k0 < K; k0 += 16) {
        float4 a4 = *(const float4*)(Ap + k0);
        float4 b4 = *(const float4*)(Bp + k0);
        As[lc+0][lr]=a4.x*rs; As[lc+1][lr]=a4.y*rs; As[lc+2][lr]=a4.z*rs; As[lc+3][lr]=a4.w*rs;
        Bs[lc+0][lr]=b4.x;    Bs[lc+1][lr]=b4.y;    Bs[lc+2][lr]=b4.z;    Bs[lc+3][lr]=b4.w;
        __syncthreads();
        #pragma unroll
        for (int kk = 0; kk < 16; kk++) {
            float ra[4], rb[4];
            *(float4*)ra = *(const float4*)&As[kk][ty*4];
            *(float4*)rb = *(const float4*)&Bs[kk][tx*4];
            #pragma unroll
            for (int i = 0; i < 4; i++)
                #pragma unroll
                for (int j = 0; j < 4; j++) acc[i][j] += ra[i] * rb[j];
        }
        __syncthreads();
    }
    #pragma unroll
    for (int i = 0; i < 4; i++) {
        int m = m0 + ty*4 + i;
        #pragma unroll
        for (int j = 0; j < 4; j++) {
            int n = n0 + tx*4 + j;
            float v = acc[i][j];
            if (bias) v += bias[n];
            if (act == 1) v = 0.5f * v * (1.0f + erff(v * 0.70710678118654752f));
            if (Cadd) v += Cadd[(size_t)m * Ncols + n];
            C[(size_t)m * Ncols + n] = v;
        }
    }
}

// ---------------- slots init: mu + clip(exp(logsigma),1e-6)*noise ----------------
__global__ void init_slots(const float* __restrict__ noise, const float* __restrict__ mu,
                           const float* __restrict__ ls) {
    int idx = blockIdx.x * 256 + threadIdx.x;   // < RBS*Dd
    int d = idx & 255;
    float sig = fmaxf(expf(ls[d]), 1e-6f);
    g_slots[idx] = mu[d] + sig * noise[idx];
}

__global__ void zero_acc() {
    int idx = blockIdx.x * 256 + threadIdx.x;   // < RBS*Dd
    g_upd[idx] = 0.f;
    if (idx < RBS) g_colsum[idx] = 0.f;
}

__global__ void rinv_k() {
    int idx = blockIdx.x * 256 + threadIdx.x;
    if (idx < RBS) g_rinv[idx] = 1.0f / (g_colsum[idx] + 1e-8f);
}

// ---------------- logits + softmax(slots) + *tw + colsum ----------------
// One thread per token; 16 slot-accumulators in registers. q tile in smem (broadcast reads).
__global__ void __launch_bounds__(256) attn_logits(const float* __restrict__ tw) {
    int b = blockIdx.y;
    int n = blockIdx.x * 256 + threadIdx.x;
    __shared__ float4 q_s[Ss * 64];     // q_s[s*64 + d4]
    for (int idx = threadIdx.x; idx < Ss * 64; idx += 256)
        q_s[idx] = reinterpret_cast<const float4*>(g_q)[b * Ss * 64 + idx];
    __syncthreads();

    float acc[Ss];
    #pragma unroll
    for (int s = 0; s < Ss; s++) acc[s] = 0.f;
    const float4* kr = reinterpret_cast<const float4*>(g_k) + ((size_t)b * Nn + n) * 64;
    #pragma unroll 4
    for (int d4 = 0; d4 < 64; d4++) {
        float4 kv = kr[d4];
        #pragma unroll
        for (int s = 0; s < Ss; s++) {
            float4 qv = q_s[s * 64 + d4];
            acc[s] += kv.x*qv.x + kv.y*qv.y + kv.z*qv.z + kv.w*qv.w;
        }
    }
    float mx = -1e30f;
    #pragma unroll
    for (int s = 0; s < Ss; s++) { acc[s] *= 0.0625f; mx = fmaxf(mx, acc[s]); }
    float sum = 0.f;
    #pragma unroll
    for (int s = 0; s < Ss; s++) { acc[s] = expf(acc[s] - mx); sum += acc[s]; }
    float twv = fmaxf(tw[(size_t)b * Nn + n], 0.f) / sum;
    #pragma unroll
    for (int s = 0; s < Ss; s++) acc[s] *= twv;

    float4* ap = reinterpret_cast<float4*>(g_attn) + ((size_t)b * Nn + n) * 4;
    ap[0] = make_float4(acc[0],  acc[1],  acc[2],  acc[3]);
    ap[1] = make_float4(acc[4],  acc[5],  acc[6],  acc[7]);
    ap[2] = make_float4(acc[8],  acc[9],  acc[10], acc[11]);
    ap[3] = make_float4(acc[12], acc[13], acc[14], acc[15]);

    __shared__ float wsum[8][Ss];
    int lane = threadIdx.x & 31, w = threadIdx.x >> 5;
    #pragma unroll
    for (int s = 0; s < Ss; s++) {
        float v = acc[s];
        #pragma unroll
        for (int o = 16; o; o >>= 1) v += __shfl_xor_sync(0xffffffffu, v, o);
        if (lane == 0) wsum[w][s] = v;
    }
    __syncthreads();
    if (threadIdx.x < Ss) {
        float tot = 0.f;
        #pragma unroll
        for (int ww = 0; ww < 8; ww++) tot += wsum[ww][threadIdx.x];
        atomicAdd(&g_colsum[b * Ss + threadIdx.x], tot);
    }
}

// ---------------- updates[b,s,d] += sum_n attn[b,n,s]*v[b,n,d] (pre-divide) ----------------
__global__ void __launch_bounds__(256) compute_updates() {
    int b = blockIdx.y;
    int n0 = blockIdx.x * 256;
    int t = threadIdx.x;
    float acc[Ss];
    #pragma unroll
    for (int s = 0; s < Ss; s++) acc[s] = 0.f;
    __shared__ float4 a_s[64];   // 16 tokens x 16 slots
    const float4* attn4 = reinterpret_cast<const float4*>(g_attn);
    for (int g = 0; g < 256; g += 16) {
        __syncthreads();
        if (t < 64) a_s[t] = attn4[((size_t)b * Nn + n0 + g) * 4 + t];
        __syncthreads();
        #pragma unroll
        for (int j = 0; j < 16; j++) {
            float vv = g_v[((size_t)b * Nn + n0 + g + j) * Dd + t];
            float4 a0 = a_s[j*4+0], a1 = a_s[j*4+1], a2 = a_s[j*4+2], a3 = a_s[j*4+3];
            acc[0]+=a0.x*vv;  acc[1]+=a0.y*vv;  acc[2]+=a0.z*vv;  acc[3]+=a0.w*vv;
            acc[4]+=a1.x*vv;  acc[5]+=a1.y*vv;  acc[6]+=a1.z*vv;  acc[7]+=a1.w*vv;
            acc[8]+=a2.x*vv;  acc[9]+=a2.y*vv;  acc[10]+=a2.z*vv; acc[11]+=a2.w*vv;
            acc[12]+=a3.x*vv; acc[13]+=a3.y*vv; acc[14]+=a3.z*vv; acc[15]+=a3.w*vv;
        }
    }
    #pragma unroll
    for (int s = 0; s < Ss; s++)
        atomicAdd(&g_upd[(b * Ss + s) * Dd + t], acc[s]);
}

// ---------------- GRU gates (torch GRUCell, order r,z,n) ----------------
__global__ void gru_gates() {
    int idx = blockIdx.x * 256 + threadIdx.x;   // < RBS*Dd
    int row = idx >> 8, d = idx & 255;
    const float* gi = g_gi + row * 768;
    const float* gh = g_gh + row * 768;
    float r  = 1.f / (1.f + expf(-(gi[d]       + gh[d])));
    float z  = 1.f / (1.f + expf(-(gi[256 + d] + gh[256 + d])));
    float nt = tanhf(gi[512 + d] + r * gh[512 + d]);
    float h = g_slots[idx];
    g_slots2[idx] = (1.f - z) * nt + z * h;
}

// ---------------- final output: [slots | normalized attn] ----------------
__global__ void writeout(float* __restrict__ out) {
    int idx = blockIdx.x * 256 + threadIdx.x;
    if (idx < RBS * Dd) {
        out[idx] = g_slots[idx];
    } else {
        int j = idx - RBS * Dd;   // j = (b*Nn+n)*16 + s
        int s = j & 15;
        int bn = j >> 4;
        int b = bn >> 12;         // / Nn
        out[idx] = g_attn[j] * g_rinv[b * Ss + s];
    }
}

// ------------------------------------------------------------------------
extern "C" void kernel_launch(void* const* d_in, const int* in_sizes, int n_in,
                              void* d_out, int out_size) {
    const float* inputs   = (const float*)d_in[0];
    const float* token_w  = (const float*)d_in[1];
    const float* noise    = (const float*)d_in[2];
    const float* ln_in_w  = (const float*)d_in[3];
    const float* ln_in_b  = (const float*)d_in[4];
    const float* ln_s_w   = (const float*)d_in[5];
    const float* ln_s_b   = (const float*)d_in[6];
    const float* ln_m_w   = (const float*)d_in[7];
    const float* ln_m_b   = (const float*)d_in[8];
    const float* Wk       = (const float*)d_in[9];
    const float* Wv       = (const float*)d_in[10];
    const float* Wq       = (const float*)d_in[11];
    const float* gru_wih  = (const float*)d_in[12];
    const float* gru_whh  = (const float*)d_in[13];
    const float* gru_bih  = (const float*)d_in[14];
    const float* gru_bhh  = (const float*)d_in[15];
    const float* mlp_w1   = (const float*)d_in[16];
    const float* mlp_b1   = (const float*)d_in[17];
    const float* mlp_w2   = (const float*)d_in[18];
    const float* mlp_b2   = (const float*)d_in[19];
    const float* slots_mu = (const float*)d_in[20];
    const float* slots_ls = (const float*)d_in[21];
    float* out = (float*)d_out;

    float *p_xln, *p_slots, *p_slots2, *p_sln, *p_q, *p_upd, *p_gi, *p_gh, *p_h, *p_rinv;
    cudaGetSymbolAddress((void**)&p_xln,   g_xln);
    cudaGetSymbolAddress((void**)&p_slots, g_slots);
    cudaGetSymbolAddress((void**)&p_slots2,g_slots2);
    cudaGetSymbolAddress((void**)&p_sln,   g_sln);
    cudaGetSymbolAddress((void**)&p_q,     g_q);
    cudaGetSymbolAddress((void**)&p_upd,   g_upd);
    cudaGetSymbolAddress((void**)&p_gi,    g_gi);
    cudaGetSymbolAddress((void**)&p_gh,    g_gh);
    cudaGetSymbolAddress((void**)&p_h,     g_hbuf);
    cudaGetSymbolAddress((void**)&p_rinv,  g_rinv);

    // x = LN(inputs); k = x@Wk^T; v = x@Wv^T
    ln_rows<<<RBN, 256>>>(inputs, p_xln, ln_in_w, ln_in_b);
    sgemm_kv<<<dim3(4, RBN / 128), 256>>>(p_xln, Wk, Wv);
    // slots = mu + sigma*noise
    init_slots<<<RBS * Dd / 256, 256>>>(noise, slots_mu, slots_ls);

    for (int it = 0; it < NITERS; ++it) {
        zero_acc<<<RBS * Dd / 256, 256>>>();
        // q = LN(slots) @ Wq^T
        ln_rows<<<RBS, 256>>>(p_slots, p_sln, ln_s_w, ln_s_b);
        gemm64<<<dim3(Dd / 64, RBS / 64), 256>>>(p_sln, Wq, nullptr, nullptr, nullptr,
                                                 p_q, RBS, Dd, Dd, 0);
        // logits -> softmax over slots -> *tw, accumulate column sums
        attn_logits<<<dim3(Nn / 256, Bb), 256>>>(token_w);
        rinv_k<<<2, 256>>>();
        // updates (pre-divide; division folded into GRU-input GEMM via rscale)
        compute_updates<<<dim3(Nn / 256, Bb), 256>>>();
        // GRU
        gemm64<<<dim3(768 / 64, RBS / 64), 256>>>(p_upd, gru_wih, gru_bih, p_rinv, nullptr,
                                                  p_gi, RBS, 768, Dd, 0);
        gemm64<<<dim3(768 / 64, RBS / 64), 256>>>(p_slots, gru_whh, gru_bhh, nullptr, nullptr,
                                                  p_gh, RBS, 768, Dd, 0);
        gru_gates<<<RBS * Dd / 256, 256>>>();
        // MLP: slots = slots2 + gelu(LN(slots2)@w1^T + b1)@w2^T + b2
        ln_rows<<<RBS, 256>>>(p_slots2, p_sln, ln_m_w, ln_m_b);
        gemm64<<<dim3(Hh / 64, RBS / 64), 256>>>(p_sln, mlp_w1, mlp_b1, nullptr, nullptr,
                                                 p_h, RBS, Hh, Dd, 1);
        gemm64<<<dim3(Dd / 64, RBS / 64), 256>>>(p_h, mlp_w2, mlp_b2, nullptr, p_slots2,
                                                 p_slots, RBS, Dd, Hh, 0);
    }
    writeout<<<(RBS * Dd + RBN * Ss) / 256, 256>>>(out);
}

// round 11
// speedup vs baseline: 1.2465x; 1.2465x over previous
#include <cuda_runtime.h>
#include <cuda_bf16.h>
#include <math.h>
#include <stdint.h>

// Problem constants
#define Bb 32
#define Nn 4096
#define Dd 256
#define Ss 16
#define Hh 512
#define NITERS 3
#define RBN (Bb*Nn)   // 131072 token rows
#define RBS (Bb*Ss)   // 512 slot rows

// ---------------- scratch (device globals; no allocation allowed) ----------------
__device__ __align__(16) __nv_bfloat16 g_a_hi[RBN*Dd];
__device__ __align__(16) __nv_bfloat16 g_a_lo[RBN*Dd];
__device__ __align__(16) __nv_bfloat16 g_w_hi[2*Dd*Dd];   // [Wk ; Wv] row-major [512,256]
__device__ __align__(16) __nv_bfloat16 g_w_lo[2*Dd*Dd];
__device__ __align__(16) float g_k   [RBN*Dd];
__device__ __align__(16) float g_v   [RBN*Dd];
__device__ __align__(16) float g_attn[RBN*Ss];     // softmax*tw (pre token-normalization)
__device__ float g_colsum[RBS];
__device__ float g_rinv  [RBS];
__device__ __align__(16) float g_slots [RBS*Dd];
__device__ __align__(16) float g_slots2[RBS*Dd];
__device__ __align__(16) float g_sln   [RBS*Dd];
__device__ __align__(16) float g_q     [RBS*Dd];
__device__ __align__(16) float g_upd   [RBS*Dd];
__device__ __align__(16) float g_gi    [RBS*3*Dd];
__device__ __align__(16) float g_gh    [RBS*3*Dd];
__device__ __align__(16) float g_hbuf  [RBS*Hh];

// ======================= mma.sync helpers (plain sm_80+ path) =======================
__device__ __forceinline__ uint32_t cvta_smem(const void* p) {
    return (uint32_t)__cvta_generic_to_shared(p);
}
#define LDSM4(r, a) \
    asm volatile("ldmatrix.sync.aligned.m8n8.x4.shared.b16 {%0,%1,%2,%3}, [%4];" \
        : "=r"((r)[0]), "=r"((r)[1]), "=r"((r)[2]), "=r"((r)[3]) : "r"(a))
// B stored [n][k] (K-major) == col-major KxN: NON-trans ldmatrix gives the
// required fragment (2 consecutive k at fixed n per thread).
#define LDSM2(r, a) \
    asm volatile("ldmatrix.sync.aligned.m8n8.x2.shared.b16 {%0,%1}, [%2];" \
        : "=r"((r)[0]), "=r"((r)[1]) : "r"(a))
#define MMA16816(d, a, b) \
    asm volatile("mma.sync.aligned.m16n8k16.row.col.f32.bf16.bf16.f32 " \
        "{%0,%1,%2,%3}, {%4,%5,%6,%7}, {%8,%9}, {%0,%1,%2,%3};" \
        : "+f"((d)[0]), "+f"((d)[1]), "+f"((d)[2]), "+f"((d)[3]) \
        : "r"((a)[0]), "r"((a)[1]), "r"((a)[2]), "r"((a)[3]), "r"((b)[0]), "r"((b)[1]))

// ---------------- input LayerNorm -> bf16 hi/lo split ----------------
__global__ void ln_rows_split(const float* __restrict__ x,
                              const float* __restrict__ w, const float* __restrict__ bias) {
    __shared__ float red[256];
    int row = blockIdx.x, t = threadIdx.x;
    size_t base = (size_t)row * Dd;
    float v = x[base + t];
    red[t] = v; __syncthreads();
    #pragma unroll
    for (int o = 128; o > 0; o >>= 1) { if (t < o) red[t] += red[t + o]; __syncthreads(); }
    float mean = red[0] * (1.0f / Dd);
    __syncthreads();
    float d = v - mean;
    red[t] = d * d; __syncthreads();
    #pragma unroll
    for (int o = 128; o > 0; o >>= 1) { if (t < o) red[t] += red[t + o]; __syncthreads(); }
    float rstd = rsqrtf(red[0] * (1.0f / Dd) + 1e-5f);
    float y = d * rstd * w[t] + bias[t];
    __nv_bfloat16 h = __float2bfloat16(y);
    g_a_hi[base + t] = h;
    g_a_lo[base + t] = __float2bfloat16(y - __bfloat162float(h));
}

// ---------------- weight split: [Wk;Wv] -> bf16 hi/lo ----------------
__global__ void wsplit(const float* __restrict__ Wk, const float* __restrict__ Wv) {
    int idx = blockIdx.x * 256 + threadIdx.x;   // < 2*Dd*Dd
    float v = (idx < Dd * Dd) ? Wk[idx] : Wv[idx - Dd * Dd];
    __nv_bfloat16 h = __float2bfloat16(v);
    g_w_hi[idx] = h;
    g_w_lo[idx] = __float2bfloat16(v - __bfloat162float(h));
}

// ---------------- HMMA GEMM: C[128,128] tile = A[128,256] @ W^T (3-way bf16 split) ----------------
// blockIdx.x = ct: {0,1} -> g_k cols [0,128)/[128,256); {2,3} -> g_v.
// blockIdx.y = m-tile. 8 warps (2 in M x 4 in N), warp tile 64x32, K chunks of 32.
__global__ void __launch_bounds__(256) hmma_kv() {
    __shared__ __align__(16) __nv_bfloat16 As_hi[128][40];
    __shared__ __align__(16) __nv_bfloat16 As_lo[128][40];
    __shared__ __align__(16) __nv_bfloat16 Bs_hi[128][40];
    __shared__ __align__(16) __nv_bfloat16 Bs_lo[128][40];

    int tid = threadIdx.x;
    int lane = tid & 31, warp = tid >> 5;
    int wm = warp & 1;        // 0..1 : 64 rows each
    int wn = warp >> 1;       // 0..3 : 32 cols each
    int ct = blockIdx.x;
    size_t m0 = (size_t)blockIdx.y * 128;
    int nbase = ct * 128;     // row block in stacked [Wk;Wv] (512 rows)

    float C[4][4][4];
    #pragma unroll
    for (int i = 0; i < 4; i++)
        #pragma unroll
        for (int j = 0; j < 4; j++)
            #pragma unroll
            for (int q = 0; q < 4; q++) C[i][j][q] = 0.f;

    for (int ch = 0; ch < 8; ch++) {
        int k0 = ch * 32;
        // cooperative load: 128 rows x 32 bf16 per tile, 4 tiles
        #pragma unroll
        for (int t2 = 0; t2 < 2; t2++) {
            int j = tid + t2 * 256;          // 0..511
            int r = j >> 2, i = (j & 3) * 8; // row, col-in-chunk
            *(uint4*)&As_hi[r][i] = *(const uint4*)&g_a_hi[(m0 + r) * Dd + k0 + i];
            *(uint4*)&As_lo[r][i] = *(const uint4*)&g_a_lo[(m0 + r) * Dd + k0 + i];
            *(uint4*)&Bs_hi[r][i] = *(const uint4*)&g_w_hi[(size_t)(nbase + r) * Dd + k0 + i];
            *(uint4*)&Bs_lo[r][i] = *(const uint4*)&g_w_lo[(size_t)(nbase + r) * Dd + k0 + i];
        }
        __syncthreads();

        #pragma unroll
        for (int ks = 0; ks < 32; ks += 16) {
            uint32_t ah[4][4], al[4][4], bh[4][2], bl[4][2];
            int arow = wm * 64 + (lane & 15);
            int acol = ks + (lane >> 4) * 8;
            #pragma unroll
            for (int mf = 0; mf < 4; mf++) {
                LDSM4(ah[mf], cvta_smem(&As_hi[arow + mf * 16][acol]));
                LDSM4(al[mf], cvta_smem(&As_lo[arow + mf * 16][acol]));
            }
            int brow = wn * 32 + (lane & 7);
            int bcol = ks + ((lane >> 3) & 1) * 8;
            #pragma unroll
            for (int nf = 0; nf < 4; nf++) {
                LDSM2(bh[nf], cvta_smem(&Bs_hi[brow + nf * 8][bcol]));
                LDSM2(bl[nf], cvta_smem(&Bs_lo[brow + nf * 8][bcol]));
            }
            #pragma unroll
            for (int mf = 0; mf < 4; mf++)
                #pragma unroll
                for (int nf = 0; nf < 4; nf++) {
                    MMA16816(C[mf][nf], ah[mf], bh[nf]);
                    MMA16816(C[mf][nf], ah[mf], bl[nf]);
                    MMA16816(C[mf][nf], al[mf], bh[nf]);
                }
        }
        __syncthreads();
    }

    // epilogue: direct global stores (float2 per fragment row)
    float* Out = (ct < 2) ? g_k : g_v;
    int ncol = (ct & 1) * 128 + wn * 32;
    #pragma unroll
    for (int mf = 0; mf < 4; mf++) {
        int row = wm * 64 + mf * 16 + (lane >> 2);
        #pragma unroll
        for (int nf = 0; nf < 4; nf++) {
            int col = ncol + nf * 8 + (lane & 3) * 2;
            float* p  = Out + (m0 + row) * Dd + col;
            float* p2 = Out + (m0 + row + 8) * Dd + col;
            *(float2*)p  = make_float2(C[mf][nf][0], C[mf][nf][1]);
            *(float2*)p2 = make_float2(C[mf][nf][2], C[mf][nf][3]);
        }
    }
}

// ---------------- generic LayerNorm (fp32 out, used for slot LNs) ----------------
__global__ void ln_rows(const float* __restrict__ x, float* __restrict__ y,
                        const float* __restrict__ w, const float* __restrict__ bias) {
    __shared__ float red[256];
    int row = blockIdx.x, t = threadIdx.x;
    size_t base = (size_t)row * Dd;
    float v = x[base + t];
    red[t] = v; __syncthreads();
    #pragma unroll
    for (int o = 128; o > 0; o >>= 1) { if (t < o) red[t] += red[t + o]; __syncthreads(); }
    float mean = red[0] * (1.0f / Dd);
    __syncthreads();
    float d = v - mean;
    red[t] = d * d; __syncthreads();
    #pragma unroll
    for (int o = 128; o > 0; o >>= 1) { if (t < o) red[t] += red[t + o]; __syncthreads(); }
    float rstd = rsqrtf(red[0] * (1.0f / Dd) + 1e-5f);
    y[base + t] = d * rstd * w[t] + bias[t];
}

// ---------------- generic small SGEMM: C = act(A@B^T + bias) (+Cadd) ----------------
__global__ void __launch_bounds__(256) gemm64(const float* __restrict__ A,
        const float* __restrict__ Bw, const float* __restrict__ bias,
        const float* __restrict__ rscale, const float* __restrict__ Cadd,
        float* __restrict__ C, int M, int Ncols, int K, int act) {
    __shared__ float As[16][64];
    __shared__ float Bs[16][64];
    int tid = threadIdx.x;
    int tx = tid & 15, ty = tid >> 4;
    int m0 = blockIdx.y * 64, n0 = blockIdx.x * 64;
    int lr = tid >> 2;           // 0..63
    int lc = (tid & 3) * 4;      // 0,4,8,12
    float rs = rscale ? rscale[m0 + lr] : 1.0f;
    const float* Ap = A  + (size_t)(m0 + lr) * K + lc;
    const float* Bp = Bw + (size_t)(n0 + lr) * K + lc;
    float acc[4][4];
    #pragma unroll
    for (int i = 0; i < 4; i++)
        #pragma unroll
        for (int j = 0; j < 4; j++) acc[i][j] = 0.f;

    for (int k0 = 0; k0 < K; k0 += 16) {
        float4 a4 = *(const float4*)(Ap + k0);
        float4 b4 = *(const float4*)(Bp + k0);
        As[lc+0][lr]=a4.x*rs; As[lc+1][lr]=a4.y*rs; As[lc+2][lr]=a4.z*rs; As[lc+3][lr]=a4.w*rs;
        Bs[lc+0][lr]=b4.x;    Bs[lc+1][lr]=b4.y;    Bs[lc+2][lr]=b4.z;    Bs[lc+3][lr]=b4.w;
        __syncthreads();
        #pragma unroll
        for (int kk = 0; kk < 16; kk++) {
            float ra[4], rb[4];
            *(float4*)ra = *(const float4*)&As[kk][ty*4];
            *(float4*)rb = *(const float4*)&Bs[kk][tx*4];
            #pragma unroll
            for (int i = 0; i < 4; i++)
                #pragma unroll
                for (int j = 0; j < 4; j++) acc[i][j] += ra[i] * rb[j];
        }
        __syncthreads();
    }
    #pragma unroll
    for (int i = 0; i < 4; i++) {
        int m = m0 + ty*4 + i;
        #pragma unroll
        for (int j = 0; j < 4; j++) {
            int n = n0 + tx*4 + j;
            float v = acc[i][j];
            if (bias) v += bias[n];
            if (act == 1) v = 0.5f * v * (1.0f + erff(v * 0.70710678118654752f));
            if (Cadd) v += Cadd[(size_t)m * Ncols + n];
            C[(size_t)m * Ncols + n] = v;
        }
    }
}

// ---------------- slots init ----------------
__global__ void init_slots(const float* __restrict__ noise, const float* __restrict__ mu,
                           const float* __restrict__ ls) {
    int idx = blockIdx.x * 256 + threadIdx.x;
    int d = idx & 255;
    float sig = fmaxf(expf(ls[d]), 1e-6f);
    g_slots[idx] = mu[d] + sig * noise[idx];
}

__global__ void zero_acc() {
    int idx = blockIdx.x * 256 + threadIdx.x;
    g_upd[idx] = 0.f;
    if (idx < RBS) g_colsum[idx] = 0.f;
}

__global__ void rinv_k() {
    int idx = blockIdx.x * 256 + threadIdx.x;
    if (idx < RBS) g_rinv[idx] = 1.0f / (g_colsum[idx] + 1e-8f);
}

// ---------------- logits + softmax(slots) + *tw + colsum ----------------
__global__ void __launch_bounds__(256) attn_logits(const float* __restrict__ tw) {
    int b = blockIdx.y;
    int n = blockIdx.x * 256 + threadIdx.x;
    __shared__ float4 q_s[Ss * 64];
    for (int idx = threadIdx.x; idx < Ss * 64; idx += 256)
        q_s[idx] = reinterpret_cast<const float4*>(g_q)[b * Ss * 64 + idx];
    __syncthreads();

    float acc[Ss];
    #pragma unroll
    for (int s = 0; s < Ss; s++) acc[s] = 0.f;
    const float4* kr = reinterpret_cast<const float4*>(g_k) + ((size_t)b * Nn + n) * 64;
    #pragma unroll 4
    for (int d4 = 0; d4 < 64; d4++) {
        float4 kv = kr[d4];
        #pragma unroll
        for (int s = 0; s < Ss; s++) {
            float4 qv = q_s[s * 64 + d4];
            acc[s] += kv.x*qv.x + kv.y*qv.y + kv.z*qv.z + kv.w*qv.w;
        }
    }
    float mx = -1e30f;
    #pragma unroll
    for (int s = 0; s < Ss; s++) { acc[s] *= 0.0625f; mx = fmaxf(mx, acc[s]); }
    float sum = 0.f;
    #pragma unroll
    for (int s = 0; s < Ss; s++) { acc[s] = expf(acc[s] - mx); sum += acc[s]; }
    float twv = fmaxf(tw[(size_t)b * Nn + n], 0.f) / sum;
    #pragma unroll
    for (int s = 0; s < Ss; s++) acc[s] *= twv;

    float4* ap = reinterpret_cast<float4*>(g_attn) + ((size_t)b * Nn + n) * 4;
    ap[0] = make_float4(acc[0],  acc[1],  acc[2],  acc[3]);
    ap[1] = make_float4(acc[4],  acc[5],  acc[6],  acc[7]);
    ap[2] = make_float4(acc[8],  acc[9],  acc[10], acc[11]);
    ap[3] = make_float4(acc[12], acc[13], acc[14], acc[15]);

    __shared__ float wsum[8][Ss];
    int lane = threadIdx.x & 31, w = threadIdx.x >> 5;
    #pragma unroll
    for (int s = 0; s < Ss; s++) {
        float v = acc[s];
        #pragma unroll
        for (int o = 16; o; o >>= 1) v += __shfl_xor_sync(0xffffffffu, v, o);
        if (lane == 0) wsum[w][s] = v;
    }
    __syncthreads();
    if (threadIdx.x < Ss) {
        float tot = 0.f;
        #pragma unroll
        for (int ww = 0; ww < 8; ww++) tot += wsum[ww][threadIdx.x];
        atomicAdd(&g_colsum[b * Ss + threadIdx.x], tot);
    }
}

// ---------------- updates[b,s,d] += sum_n attn[b,n,s]*v[b,n,d] ----------------
__global__ void __launch_bounds__(256) compute_updates() {
    int b = blockIdx.y;
    int n0 = blockIdx.x * 256;
    int t = threadIdx.x;
    float acc[Ss];
    #pragma unroll
    for (int s = 0; s < Ss; s++) acc[s] = 0.f;
    __shared__ float4 a_s[64];
    const float4* attn4 = reinterpret_cast<const float4*>(g_attn);
    for (int g = 0; g < 256; g += 16) {
        __syncthreads();
        if (t < 64) a_s[t] = attn4[((size_t)b * Nn + n0 + g) * 4 + t];
        __syncthreads();
        #pragma unroll
        for (int j = 0; j < 16; j++) {
            float vv = g_v[((size_t)b * Nn + n0 + g + j) * Dd + t];
            float4 a0 = a_s[j*4+0], a1 = a_s[j*4+1], a2 = a_s[j*4+2], a3 = a_s[j*4+3];
            acc[0]+=a0.x*vv;  acc[1]+=a0.y*vv;  acc[2]+=a0.z*vv;  acc[3]+=a0.w*vv;
            acc[4]+=a1.x*vv;  acc[5]+=a1.y*vv;  acc[6]+=a1.z*vv;  acc[7]+=a1.w*vv;
            acc[8]+=a2.x*vv;  acc[9]+=a2.y*vv;  acc[10]+=a2.z*vv; acc[11]+=a2.w*vv;
            acc[12]+=a3.x*vv; acc[13]+=a3.y*vv; acc[14]+=a3.z*vv; acc[15]+=a3.w*vv;
        }
    }
    #pragma unroll
    for (int s = 0; s < Ss; s++)
        atomicAdd(&g_upd[(b * Ss + s) * Dd + t], acc[s]);
}

// ---------------- GRU gates ----------------
__global__ void gru_gates() {
    int idx = blockIdx.x * 256 + threadIdx.x;
    int row = idx >> 8, d = idx & 255;
    const float* gi = g_gi + row * 768;
    const float* gh = g_gh + row * 768;
    float r  = 1.f / (1.f + expf(-(gi[d]       + gh[d])));
    float z  = 1.f / (1.f + expf(-(gi[256 + d] + gh[256 + d])));
    float nt = tanhf(gi[512 + d] + r * gh[512 + d]);
    float h = g_slots[idx];
    g_slots2[idx] = (1.f - z) * nt + z * h;
}

// ---------------- final output: [slots | normalized attn] ----------------
__global__ void writeout(float* __restrict__ out) {
    int idx = blockIdx.x * 256 + threadIdx.x;
    if (idx < RBS * Dd) {
        out[idx] = g_slots[idx];
    } else {
        int j = idx - RBS * Dd;
        int s = j & 15;
        int bn = j >> 4;
        int b = bn >> 12;
        out[idx] = g_attn[j] * g_rinv[b * Ss + s];
    }
}

// ------------------------------------------------------------------------
extern "C" void kernel_launch(void* const* d_in, const int* in_sizes, int n_in,
                              void* d_out, int out_size) {
    const float* inputs   = (const float*)d_in[0];
    const float* token_w  = (const float*)d_in[1];
    const float* noise    = (const float*)d_in[2];
    const float* ln_in_w  = (const float*)d_in[3];
    const float* ln_in_b  = (const float*)d_in[4];
    const float* ln_s_w   = (const float*)d_in[5];
    const float* ln_s_b   = (const float*)d_in[6];
    const float* ln_m_w   = (const float*)d_in[7];
    const float* ln_m_b   = (const float*)d_in[8];
    const float* Wk       = (const float*)d_in[9];
    const float* Wv       = (const float*)d_in[10];
    const float* Wq       = (const float*)d_in[11];
    const float* gru_wih  = (const float*)d_in[12];
    const float* gru_whh  = (const float*)d_in[13];
    const float* gru_bih  = (const float*)d_in[14];
    const float* gru_bhh  = (const float*)d_in[15];
    const float* mlp_w1   = (const float*)d_in[16];
    const float* mlp_b1   = (const float*)d_in[17];
    const float* mlp_w2   = (const float*)d_in[18];
    const float* mlp_b2   = (const float*)d_in[19];
    const float* slots_mu = (const float*)d_in[20];
    const float* slots_ls = (const float*)d_in[21];
    float* out = (float*)d_out;

    float *p_slots, *p_slots2, *p_sln, *p_q, *p_upd, *p_gi, *p_gh, *p_h, *p_rinv;
    cudaGetSymbolAddress((void**)&p_slots, g_slots);
    cudaGetSymbolAddress((void**)&p_slots2,g_slots2);
    cudaGetSymbolAddress((void**)&p_sln,   g_sln);
    cudaGetSymbolAddress((void**)&p_q,     g_q);
    cudaGetSymbolAddress((void**)&p_upd,   g_upd);
    cudaGetSymbolAddress((void**)&p_gi,    g_gi);
    cudaGetSymbolAddress((void**)&p_gh,    g_gh);
    cudaGetSymbolAddress((void**)&p_h,     g_hbuf);
    cudaGetSymbolAddress((void**)&p_rinv,  g_rinv);

    // x = LN(inputs) -> bf16 hi/lo; weights -> bf16 hi/lo; k/v via mma.sync bf16
    ln_rows_split<<<RBN, 256>>>(inputs, ln_in_w, ln_in_b);
    wsplit<<<2 * Dd * Dd / 256, 256>>>(Wk, Wv);
    hmma_kv<<<dim3(4, RBN / 128), 256>>>();
    init_slots<<<RBS * Dd / 256, 256>>>(noise, slots_mu, slots_ls);

    for (int it = 0; it < NITERS; ++it) {
        zero_acc<<<RBS * Dd / 256, 256>>>();
        ln_rows<<<RBS, 256>>>(p_slots, p_sln, ln_s_w, ln_s_b);
        gemm64<<<dim3(Dd / 64, RBS / 64), 256>>>(p_sln, Wq, nullptr, nullptr, nullptr,
                                                 p_q, RBS, Dd, Dd, 0);
        attn_logits<<<dim3(Nn / 256, Bb), 256>>>(token_w);
        rinv_k<<<2, 256>>>();
        compute_updates<<<dim3(Nn / 256, Bb), 256>>>();
        gemm64<<<dim3(768 / 64, RBS / 64), 256>>>(p_upd, gru_wih, gru_bih, p_rinv, nullptr,
                                                  p_gi, RBS, 768, Dd, 0);
        gemm64<<<dim3(768 / 64, RBS / 64), 256>>>(p_slots, gru_whh, gru_bhh, nullptr, nullptr,
                                                  p_gh, RBS, 768, Dd, 0);
        gru_gates<<<RBS * Dd / 256, 256>>>();
        ln_rows<<<RBS, 256>>>(p_slots2, p_sln, ln_m_w, ln_m_b);
        gemm64<<<dim3(Hh / 64, RBS / 64), 256>>>(p_sln, mlp_w1, mlp_b1, nullptr, nullptr,
                                                 p_h, RBS, Hh, Dd, 1);
        gemm64<<<dim3(Dd / 64, RBS / 64), 256>>>(p_h, mlp_w2, mlp_b2, nullptr, p_slots2,
                                                 p_slots, RBS, Dd, Hh, 0);
    }
    writeout<<<(RBS * Dd + RBN * Ss) / 256, 256>>>(out);
}

// round 14
// speedup vs baseline: 1.3904x; 1.1155x over previous
#include <cuda_runtime.h>
#include <cuda_bf16.h>
#include <math.h>
#include <stdint.h>

// Problem constants
#define Bb 32
#define Nn 4096
#define Dd 256
#define Ss 16
#define Hh 512
#define NITERS 3
#define RBN (Bb*Nn)   // 131072 token rows
#define RBS (Bb*Ss)   // 512 slot rows

// ---------------- scratch (device globals; no allocation allowed) ----------------
__device__ __align__(16) __nv_bfloat16 g_a_hi[RBN*Dd];
__device__ __align__(16) __nv_bfloat16 g_a_lo[RBN*Dd];
__device__ __align__(16) __nv_bfloat16 g_w_hi[2*Dd*Dd];   // [Wk ; Wv] row-major [512,256]
__device__ __align__(16) __nv_bfloat16 g_w_lo[2*Dd*Dd];
__device__ __align__(16) float g_k   [RBN*Dd];
__device__ __align__(16) float g_v   [RBN*Dd];
__device__ __align__(16) float g_attn[RBN*Ss];     // softmax*tw (pre token-normalization)
__device__ float g_colsum[RBS];
__device__ float g_rinv  [RBS];
__device__ __align__(16) float g_slots [RBS*Dd];
__device__ __align__(16) float g_slots2[RBS*Dd];
__device__ __align__(16) float g_sln   [RBS*Dd];
__device__ __align__(16) float g_q     [RBS*Dd];
__device__ __align__(16) float g_upd   [RBS*Dd];
__device__ __align__(16) float g_gi    [RBS*3*Dd];
__device__ __align__(16) float g_gh    [RBS*3*Dd];
__device__ __align__(16) float g_hbuf  [RBS*Hh];

// ======================= mma.sync helpers (plain sm_80+ path) =======================
__device__ __forceinline__ uint32_t cvta_smem(const void* p) {
    return (uint32_t)__cvta_generic_to_shared(p);
}
#define LDSM4(r, a) \
    asm volatile("ldmatrix.sync.aligned.m8n8.x4.shared.b16 {%0,%1,%2,%3}, [%4];" \
        : "=r"((r)[0]), "=r"((r)[1]), "=r"((r)[2]), "=r"((r)[3]) : "r"(a))
// B stored [n][k] (K-major) == col-major KxN: NON-trans ldmatrix gives the
// required fragment (2 consecutive k at fixed n per thread).
#define LDSM2(r, a) \
    asm volatile("ldmatrix.sync.aligned.m8n8.x2.shared.b16 {%0,%1}, [%2];" \
        : "=r"((r)[0]), "=r"((r)[1]) : "r"(a))
#define MMA16816(d, a, b) \
    asm volatile("mma.sync.aligned.m16n8k16.row.col.f32.bf16.bf16.f32 " \
        "{%0,%1,%2,%3}, {%4,%5,%6,%7}, {%8,%9}, {%0,%1,%2,%3};" \
        : "+f"((d)[0]), "+f"((d)[1]), "+f"((d)[2]), "+f"((d)[3]) \
        : "r"((a)[0]), "r"((a)[1]), "r"((a)[2]), "r"((a)[3]), "r"((b)[0]), "r"((b)[1]))
#define CP_ASYNC16(dst, src) \
    asm volatile("cp.async.cg.shared.global [%0], [%1], 16;" :: "r"(dst), "l"(src))
#define CP_COMMIT() asm volatile("cp.async.commit_group;" ::: "memory")
#define CP_WAIT1()  asm volatile("cp.async.wait_group 1;" ::: "memory")
#define CP_WAIT0()  asm volatile("cp.async.wait_group 0;" ::: "memory")

// ---------------- input LayerNorm -> bf16 hi/lo split (shuffle reduction) ----------------
__global__ void ln_rows_split(const float* __restrict__ x,
                              const float* __restrict__ w, const float* __restrict__ bias) {
    __shared__ float w1[8], w2[8];
    int row = blockIdx.x, t = threadIdx.x;
    int lane = t & 31, wid = t >> 5;
    size_t base = (size_t)row * Dd;
    float v = x[base + t];
    float s1 = v, s2 = v * v;
    #pragma unroll
    for (int o = 16; o; o >>= 1) {
        s1 += __shfl_xor_sync(0xffffffffu, s1, o);
        s2 += __shfl_xor_sync(0xffffffffu, s2, o);
    }
    if (lane == 0) { w1[wid] = s1; w2[wid] = s2; }
    __syncthreads();
    float S1 = 0.f, S2 = 0.f;
    #pragma unroll
    for (int i = 0; i < 8; i++) { S1 += w1[i]; S2 += w2[i]; }
    float mean = S1 * (1.0f / Dd);
    float var  = S2 * (1.0f / Dd) - mean * mean;
    float rstd = rsqrtf(var + 1e-5f);
    float y = (v - mean) * rstd * w[t] + bias[t];
    __nv_bfloat16 h = __float2bfloat16(y);
    g_a_hi[base + t] = h;
    g_a_lo[base + t] = __float2bfloat16(y - __bfloat162float(h));
}

// ---------------- weight split: [Wk;Wv] -> bf16 hi/lo ----------------
__global__ void wsplit(const float* __restrict__ Wk, const float* __restrict__ Wv) {
    int idx = blockIdx.x * 256 + threadIdx.x;   // < 2*Dd*Dd
    float v = (idx < Dd * Dd) ? Wk[idx] : Wv[idx - Dd * Dd];
    __nv_bfloat16 h = __float2bfloat16(v);
    g_w_hi[idx] = h;
    g_w_lo[idx] = __float2bfloat16(v - __bfloat162float(h));
}

// ---------------- HMMA GEMM v2: cp.async double-buffered ----------------
// blockIdx.x = ct: {0,1} -> g_k cols [0,128)/[128,256); {2,3} -> g_v.
// blockIdx.y = m-tile. 8 warps (2 in M x 4 in N), warp tile 64x32, K chunks of 32.
// smem: 2 stages x 4 tiles (AHI,ALO,BHI,BLO) x 128 rows x 40 elems (80B stride, conflict-free)
#define TSZ 5120            // elements per tile (128*40)
#define STG (4*TSZ)         // elements per stage
#define SMEM_BYTES (2*STG*2)

__device__ __forceinline__ void kv_load_stage(__nv_bfloat16* base, int tid,
                                              size_t m0, int nbase, int k0) {
    uint32_t sb = cvta_smem(base);
    #pragma unroll
    for (int t2 = 0; t2 < 2; t2++) {
        int j = tid + t2 * 256;          // 0..511
        int r = j >> 2, i = (j & 3) * 8; // row, col-in-chunk
        uint32_t soff = (uint32_t)(r * 40 + i) * 2;
        CP_ASYNC16(sb + 0 * TSZ * 2 + soff, &g_a_hi[(m0 + r) * Dd + k0 + i]);
        CP_ASYNC16(sb + 1 * TSZ * 2 + soff, &g_a_lo[(m0 + r) * Dd + k0 + i]);
        CP_ASYNC16(sb + 2 * TSZ * 2 + soff, &g_w_hi[(size_t)(nbase + r) * Dd + k0 + i]);
        CP_ASYNC16(sb + 3 * TSZ * 2 + soff, &g_w_lo[(size_t)(nbase + r) * Dd + k0 + i]);
    }
}

__global__ void __launch_bounds__(256) hmma_kv() {
    extern __shared__ __nv_bfloat16 sm[];
    int tid = threadIdx.x;
    int lane = tid & 31, warp = tid >> 5;
    int wm = warp & 1;        // 0..1 : 64 rows each
    int wn = warp >> 1;       // 0..3 : 32 cols each
    int ct = blockIdx.x;
    size_t m0 = (size_t)blockIdx.y * 128;
    int nbase = ct * 128;     // row block in stacked [Wk;Wv] (512 rows)

    float C[4][4][4];
    #pragma unroll
    for (int i = 0; i < 4; i++)
        #pragma unroll
        for (int j = 0; j < 4; j++)
            #pragma unroll
            for (int q = 0; q < 4; q++) C[i][j][q] = 0.f;

    kv_load_stage(sm, tid, m0, nbase, 0);
    CP_COMMIT();

    for (int ch = 0; ch < 8; ch++) {
        int buf = ch & 1;
        if (ch < 7) {
            kv_load_stage(sm + ((ch + 1) & 1) * STG, tid, m0, nbase, (ch + 1) * 32);
            CP_COMMIT();
            CP_WAIT1();
        } else {
            CP_WAIT0();
        }
        __syncthreads();

        const __nv_bfloat16* Ah = sm + buf * STG;
        const __nv_bfloat16* Al = Ah + TSZ;
        const __nv_bfloat16* Bh = Ah + 2 * TSZ;
        const __nv_bfloat16* Bl = Ah + 3 * TSZ;

        #pragma unroll
        for (int ks = 0; ks < 32; ks += 16) {
            uint32_t ah[4][4], al[4][4], bh[4][2], bl[4][2];
            int arow = wm * 64 + (lane & 15);
            int acol = ks + (lane >> 4) * 8;
            #pragma unroll
            for (int mf = 0; mf < 4; mf++) {
                LDSM4(ah[mf], cvta_smem(&Ah[(arow + mf * 16) * 40 + acol]));
                LDSM4(al[mf], cvta_smem(&Al[(arow + mf * 16) * 40 + acol]));
            }
            int brow = wn * 32 + (lane & 7);
            int bcol = ks + ((lane >> 3) & 1) * 8;
            #pragma unroll
            for (int nf = 0; nf < 4; nf++) {
                LDSM2(bh[nf], cvta_smem(&Bh[(brow + nf * 8) * 40 + bcol]));
                LDSM2(bl[nf], cvta_smem(&Bl[(brow + nf * 8) * 40 + bcol]));
            }
            #pragma unroll
            for (int mf = 0; mf < 4; mf++)
                #pragma unroll
                for (int nf = 0; nf < 4; nf++) {
                    MMA16816(C[mf][nf], ah[mf], bh[nf]);
                    MMA16816(C[mf][nf], ah[mf], bl[nf]);
                    MMA16816(C[mf][nf], al[mf], bh[nf]);
                }
        }
        __syncthreads();
    }

    // epilogue: direct global stores (float2 per fragment row)
    float* Out = (ct < 2) ? g_k : g_v;
    int ncol = (ct & 1) * 128 + wn * 32;
    #pragma unroll
    for (int mf = 0; mf < 4; mf++) {
        int row = wm * 64 + mf * 16 + (lane >> 2);
        #pragma unroll
        for (int nf = 0; nf < 4; nf++) {
            int col = ncol + nf * 8 + (lane & 3) * 2;
            float* p  = Out + (m0 + row) * Dd + col;
            float* p2 = Out + (m0 + row + 8) * Dd + col;
            *(float2*)p  = make_float2(C[mf][nf][0], C[mf][nf][1]);
            *(float2*)p2 = make_float2(C[mf][nf][2], C[mf][nf][3]);
        }
    }
}

// ---------------- generic LayerNorm (fp32 out; shuffle reduction) ----------------
__global__ void ln_rows(const float* __restrict__ x, float* __restrict__ y,
                        const float* __restrict__ w, const float* __restrict__ bias) {
    __shared__ float w1[8], w2[8];
    int row = blockIdx.x, t = threadIdx.x;
    int lane = t & 31, wid = t >> 5;
    size_t base = (size_t)row * Dd;
    float v = x[base + t];
    float s1 = v, s2 = v * v;
    #pragma unroll
    for (int o = 16; o; o >>= 1) {
        s1 += __shfl_xor_sync(0xffffffffu, s1, o);
        s2 += __shfl_xor_sync(0xffffffffu, s2, o);
    }
    if (lane == 0) { w1[wid] = s1; w2[wid] = s2; }
    __syncthreads();
    float S1 = 0.f, S2 = 0.f;
    #pragma unroll
    for (int i = 0; i < 8; i++) { S1 += w1[i]; S2 += w2[i]; }
    float mean = S1 * (1.0f / Dd);
    float var  = S2 * (1.0f / Dd) - mean * mean;
    float rstd = rsqrtf(var + 1e-5f);
    y[base + t] = (v - mean) * rstd * w[t] + bias[t];
}

// ---------------- generic small SGEMM: C = act(A@B^T + bias) (+Cadd) ----------------
__global__ void __launch_bounds__(256) gemm64(const float* __restrict__ A,
        const float* __restrict__ Bw, const float* __restrict__ bias,
        const float* __restrict__ rscale, const float* __restrict__ Cadd,
        float* __restrict__ C, int M, int Ncols, int K, int act) {
    __shared__ float As[16][64];
    __shared__ float Bs[16][64];
    int tid = threadIdx.x;
    int tx = tid & 15, ty = tid >> 4;
    int m0 = blockIdx.y * 64, n0 = blockIdx.x * 64;
    int lr = tid >> 2;           // 0..63
    int lc = (tid & 3) * 4;      // 0,4,8,12
    float rs = rscale ? rscale[m0 + lr] : 1.0f;
    const float* Ap = A  + (size_t)(m0 + lr) * K + lc;
    const float* Bp = Bw + (size_t)(n0 + lr) * K + lc;
    float acc[4][4];
    #pragma unroll
    for (int i = 0; i < 4; i++)
        #pragma unroll
        for (int j = 0; j < 4; j++) acc[i][j] = 0.f;

    for (int k0 = 0; k0 < K; k0 += 16) {
        float4 a4 = *(const float4*)(Ap + k0);
        float4 b4 = *(const float4*)(Bp + k0);
        As[lc+0][lr]=a4.x*rs; As[lc+1][lr]=a4.y*rs; As[lc+2][lr]=a4.z*rs; As[lc+3][lr]=a4.w*rs;
        Bs[lc+0][lr]=b4.x;    Bs[lc+1][lr]=b4.y;    Bs[lc+2][lr]=b4.z;    Bs[lc+3][lr]=b4.w;
        __syncthreads();
        #pragma unroll
        for (int kk = 0; kk < 16; kk++) {
            float ra[4], rb[4];
            *(float4*)ra = *(const float4*)&As[kk][ty*4];
            *(float4*)rb = *(const float4*)&Bs[kk][tx*4];
            #pragma unroll
            for (int i = 0; i < 4; i++)
                #pragma unroll
                for (int j = 0; j < 4; j++) acc[i][j] += ra[i] * rb[j];
        }
        __syncthreads();
    }
    #pragma unroll
    for (int i = 0; i < 4; i++) {
        int m = m0 + ty*4 + i;
        #pragma unroll
        for (int j = 0; j < 4; j++) {
            int n = n0 + tx*4 + j;
            float v = acc[i][j];
            if (bias) v += bias[n];
            if (act == 1) v = 0.5f * v * (1.0f + erff(v * 0.70710678118654752f));
            if (Cadd) v += Cadd[(size_t)m * Ncols + n];
            C[(size_t)m * Ncols + n] = v;
        }
    }
}

// ---------------- slots init ----------------
__global__ void init_slots(const float* __restrict__ noise, const float* __restrict__ mu,
                           const float* __restrict__ ls) {
    int idx = blockIdx.x * 256 + threadIdx.x;
    int d = idx & 255;
    float sig = fmaxf(expf(ls[d]), 1e-6f);
    g_slots[idx] = mu[d] + sig * noise[idx];
}

__global__ void zero_acc() {
    int idx = blockIdx.x * 256 + threadIdx.x;
    g_upd[idx] = 0.f;
    if (idx < RBS) g_colsum[idx] = 0.f;
}

__global__ void rinv_k() {
    int idx = blockIdx.x * 256 + threadIdx.x;
    if (idx < RBS) g_rinv[idx] = 1.0f / (g_colsum[idx] + 1e-8f);
}

// ---------------- logits + softmax(slots) + *tw + colsum ----------------
__global__ void __launch_bounds__(256) attn_logits(const float* __restrict__ tw) {
    int b = blockIdx.y;
    int n = blockIdx.x * 256 + threadIdx.x;
    __shared__ float4 q_s[Ss * 64];
    for (int idx = threadIdx.x; idx < Ss * 64; idx += 256)
        q_s[idx] = reinterpret_cast<const float4*>(g_q)[b * Ss * 64 + idx];
    __syncthreads();

    float acc[Ss];
    #pragma unroll
    for (int s = 0; s < Ss; s++) acc[s] = 0.f;
    const float4* kr = reinterpret_cast<const float4*>(g_k) + ((size_t)b * Nn + n) * 64;
    #pragma unroll 4
    for (int d4 = 0; d4 < 64; d4++) {
        float4 kv = kr[d4];
        #pragma unroll
        for (int s = 0; s < Ss; s++) {
            float4 qv = q_s[s * 64 + d4];
            acc[s] += kv.x*qv.x + kv.y*qv.y + kv.z*qv.z + kv.w*qv.w;
        }
    }
    float mx = -1e30f;
    #pragma unroll
    for (int s = 0; s < Ss; s++) { acc[s] *= 0.0625f; mx = fmaxf(mx, acc[s]); }
    float sum = 0.f;
    #pragma unroll
    for (int s = 0; s < Ss; s++) { acc[s] = expf(acc[s] - mx); sum += acc[s]; }
    float twv = fmaxf(tw[(size_t)b * Nn + n], 0.f) / sum;
    #pragma unroll
    for (int s = 0; s < Ss; s++) acc[s] *= twv;

    float4* ap = reinterpret_cast<float4*>(g_attn) + ((size_t)b * Nn + n) * 4;
    ap[0] = make_float4(acc[0],  acc[1],  acc[2],  acc[3]);
    ap[1] = make_float4(acc[4],  acc[5],  acc[6],  acc[7]);
    ap[2] = make_float4(acc[8],  acc[9],  acc[10], acc[11]);
    ap[3] = make_float4(acc[12], acc[13], acc[14], acc[15]);

    __shared__ float wsum[8][Ss];
    int lane = threadIdx.x & 31, w = threadIdx.x >> 5;
    #pragma unroll
    for (int s = 0; s < Ss; s++) {
        float v = acc[s];
        #pragma unroll
        for (int o = 16; o; o >>= 1) v += __shfl_xor_sync(0xffffffffu, v, o);
        if (lane == 0) wsum[w][s] = v;
    }
    __syncthreads();
    if (threadIdx.x < Ss) {
        float tot = 0.f;
        #pragma unroll
        for (int ww = 0; ww < 8; ww++) tot += wsum[ww][threadIdx.x];
        atomicAdd(&g_colsum[b * Ss + threadIdx.x], tot);
    }
}

// ---------------- updates[b,s,d] += sum_n attn[b,n,s]*v[b,n,d] ----------------
__global__ void __launch_bounds__(256) compute_updates() {
    int b = blockIdx.y;
    int n0 = blockIdx.x * 256;
    int t = threadIdx.x;
    float acc[Ss];
    #pragma unroll
    for (int s = 0; s < Ss; s++) acc[s] = 0.f;
    __shared__ float4 a_s[64];
    const float4* attn4 = reinterpret_cast<const float4*>(g_attn);
    for (int g = 0; g < 256; g += 16) {
        __syncthreads();
        if (t < 64) a_s[t] = attn4[((size_t)b * Nn + n0 + g) * 4 + t];
        __syncthreads();
        #pragma unroll
        for (int j = 0; j < 16; j++) {
            float vv = g_v[((size_t)b * Nn + n0 + g + j) * Dd + t];
            float4 a0 = a_s[j*4+0], a1 = a_s[j*4+1], a2 = a_s[j*4+2], a3 = a_s[j*4+3];
            acc[0]+=a0.x*vv;  acc[1]+=a0.y*vv;  acc[2]+=a0.z*vv;  acc[3]+=a0.w*vv;
            acc[4]+=a1.x*vv;  acc[5]+=a1.y*vv;  acc[6]+=a1.z*vv;  acc[7]+=a1.w*vv;
            acc[8]+=a2.x*vv;  acc[9]+=a2.y*vv;  acc[10]+=a2.z*vv; acc[11]+=a2.w*vv;
            acc[12]+=a3.x*vv; acc[13]+=a3.y*vv; acc[14]+=a3.z*vv; acc[15]+=a3.w*vv;
        }
    }
    #pragma unroll
    for (int s = 0; s < Ss; s++)
        atomicAdd(&g_upd[(b * Ss + s) * Dd + t], acc[s]);
}

// ---------------- GRU gates ----------------
__global__ void gru_gates() {
    int idx = blockIdx.x * 256 + threadIdx.x;
    int row = idx >> 8, d = idx & 255;
    const float* gi = g_gi + row * 768;
    const float* gh = g_gh + row * 768;
    float r  = 1.f / (1.f + expf(-(gi[d]       + gh[d])));
    float z  = 1.f / (1.f + expf(-(gi[256 + d] + gh[256 + d])));
    float nt = tanhf(gi[512 + d] + r * gh[512 + d]);
    float h = g_slots[idx];
    g_slots2[idx] = (1.f - z) * nt + z * h;
}

// ---------------- final output: [slots | normalized attn] ----------------
__global__ void writeout(float* __restrict__ out) {
    int idx = blockIdx.x * 256 + threadIdx.x;
    if (idx < RBS * Dd) {
        out[idx] = g_slots[idx];
    } else {
        int j = idx - RBS * Dd;
        int s = j & 15;
        int bn = j >> 4;
        int b = bn >> 12;
        out[idx] = g_attn[j] * g_rinv[b * Ss + s];
    }
}

// ------------------------------------------------------------------------
extern "C" void kernel_launch(void* const* d_in, const int* in_sizes, int n_in,
                              void* d_out, int out_size) {
    const float* inputs   = (const float*)d_in[0];
    const float* token_w  = (const float*)d_in[1];
    const float* noise    = (const float*)d_in[2];
    const float* ln_in_w  = (const float*)d_in[3];
    const float* ln_in_b  = (const float*)d_in[4];
    const float* ln_s_w   = (const float*)d_in[5];
    const float* ln_s_b   = (const float*)d_in[6];
    const float* ln_m_w   = (const float*)d_in[7];
    const float* ln_m_b   = (const float*)d_in[8];
    const float* Wk       = (const float*)d_in[9];
    const float* Wv       = (const float*)d_in[10];
    const float* Wq       = (const float*)d_in[11];
    const float* gru_wih  = (const float*)d_in[12];
    const float* gru_whh  = (const float*)d_in[13];
    const float* gru_bih  = (const float*)d_in[14];
    const float* gru_bhh  = (const float*)d_in[15];
    const float* mlp_w1   = (const float*)d_in[16];
    const float* mlp_b1   = (const float*)d_in[17];
    const float* mlp_w2   = (const float*)d_in[18];
    const float* mlp_b2   = (const float*)d_in[19];
    const float* slots_mu = (const float*)d_in[20];
    const float* slots_ls = (const float*)d_in[21];
    float* out = (float*)d_out;

    float *p_slots, *p_slots2, *p_sln, *p_q, *p_upd, *p_gi, *p_gh, *p_h, *p_rinv;
    cudaGetSymbolAddress((void**)&p_slots, g_slots);
    cudaGetSymbolAddress((void**)&p_slots2,g_slots2);
    cudaGetSymbolAddress((void**)&p_sln,   g_sln);
    cudaGetSymbolAddress((void**)&p_q,     g_q);
    cudaGetSymbolAddress((void**)&p_upd,   g_upd);
    cudaGetSymbolAddress((void**)&p_gi,    g_gi);
    cudaGetSymbolAddress((void**)&p_gh,    g_gh);
    cudaGetSymbolAddress((void**)&p_h,     g_hbuf);
    cudaGetSymbolAddress((void**)&p_rinv,  g_rinv);

    cudaFuncSetAttribute(hmma_kv, cudaFuncAttributeMaxDynamicSharedMemorySize, SMEM_BYTES);

    // x = LN(inputs) -> bf16 hi/lo; weights -> bf16 hi/lo; k/v via mma.sync bf16
    ln_rows_split<<<RBN, 256>>>(inputs, ln_in_w, ln_in_b);
    wsplit<<<2 * Dd * Dd / 256, 256>>>(Wk, Wv);
    hmma_kv<<<dim3(4, RBN / 128), 256, SMEM_BYTES>>>();
    init_slots<<<RBS * Dd / 256, 256>>>(noise, slots_mu, slots_ls);

    for (int it = 0; it < NITERS; ++it) {
        zero_acc<<<RBS * Dd / 256, 256>>>();
        ln_rows<<<RBS, 256>>>(p_slots, p_sln, ln_s_w, ln_s_b);
        gemm64<<<dim3(Dd / 64, RBS / 64), 256>>>(p_sln, Wq, nullptr, nullptr, nullptr,
                                                 p_q, RBS, Dd, Dd, 0);
        attn_logits<<<dim3(Nn / 256, Bb), 256>>>(token_w);
        rinv_k<<<2, 256>>>();
        compute_updates<<<dim3(Nn / 256, Bb), 256>>>();
        gemm64<<<dim3(768 / 64, RBS / 64), 256>>>(p_upd, gru_wih, gru_bih, p_rinv, nullptr,
                                                  p_gi, RBS, 768, Dd, 0);
        gemm64<<<dim3(768 / 64, RBS / 64), 256>>>(p_slots, gru_whh, gru_bhh, nullptr, nullptr,
                                                  p_gh, RBS, 768, Dd, 0);
        gru_gates<<<RBS * Dd / 256, 256>>>();
        ln_rows<<<RBS, 256>>>(p_slots2, p_sln, ln_m_w, ln_m_b);
        gemm64<<<dim3(Hh / 64, RBS / 64), 256>>>(p_sln, mlp_w1, mlp_b1, nullptr, nullptr,
                                                 p_h, RBS, Hh, Dd, 1);
        gemm64<<<dim3(Dd / 64, RBS / 64), 256>>>(p_h, mlp_w2, mlp_b2, nullptr, p_slots2,
                                                 p_slots, RBS, Dd, Hh, 0);
    }
    writeout<<<(RBS * Dd + RBN * Ss) / 256, 256>>>(out);
}